// round 5
// baseline (speedup 1.0000x reference)
#include <cuda_runtime.h>
#include <cstdint>

#define FULL_MASK 0xffffffffu

__device__ __forceinline__ unsigned long long pack2(float lo, float hi) {
    unsigned long long r;
    asm("mov.b64 %0, {%1, %2};" : "=l"(r) : "f"(lo), "f"(hi));
    return r;
}
__device__ __forceinline__ unsigned long long dup2(float v) {
    unsigned long long r;
    asm("mov.b64 %0, {%1, %1};" : "=l"(r) : "f"(v));
    return r;
}
__device__ __forceinline__ void unpack2(unsigned long long v, float& lo, float& hi) {
    asm("mov.b64 {%0, %1}, %2;" : "=f"(lo), "=f"(hi) : "l"(v));
}
// d = a * b + d   (packed 2x fp32, Blackwell f32x2 pipe — 2 FMAs/instr)
__device__ __forceinline__ void fma2(unsigned long long& d, unsigned long long a, unsigned long long b) {
    asm("fma.rn.f32x2 %0, %1, %2, %0;" : "+l"(d) : "l"(a), "l"(b));
}
__device__ __forceinline__ unsigned long long add2(unsigned long long a, unsigned long long b) {
    unsigned long long r;
    asm("add.rn.f32x2 %0, %1, %2;" : "=l"(r) : "l"(a), "l"(b));
    return r;
}
// streaming (evict-first) 128-bit global load/store — x and out are single-touch
__device__ __forceinline__ float4 ldg_cs(const float4* p) {
    float4 v;
    asm volatile("ld.global.cs.v4.f32 {%0,%1,%2,%3}, [%4];"
                 : "=f"(v.x), "=f"(v.y), "=f"(v.z), "=f"(v.w) : "l"(p));
    return v;
}
__device__ __forceinline__ void stg_cs(float4* p, float4 v) {
    asm volatile("st.global.cs.v4.f32 [%0], {%1,%2,%3,%4};"
                 :: "l"(p), "f"(v.x), "f"(v.y), "f"(v.z), "f"(v.w));
}

// Analytic collapse of the quantum circuit:
//   xang = x @ W_in^T + b_in
//   Heisenberg: U† Z_w U = Z_0 Z_1 ... Z_w (CNOT chain); product input state =>
//   z_w = prod_{j<=w} cos(theta_j) * cos(xang_j)
//   out  = relu(z @ W_out^T + b_out)
//
// Block = 128 threads, 2 CTAs/SM. Each thread owns 8 E-columns
// (cA..cA+3, cB..cB+3) for both GEMMs; all weights in registers.
// 2 tokens/iteration, distance-1 prefetch, double-buffered reduce scratch.
__global__ void __launch_bounds__(128, 2)
qff_kernel(const float* __restrict__ x,
           const float* __restrict__ W_in,
           const float* __restrict__ b_in,
           const float* __restrict__ theta,
           const float* __restrict__ W_out,
           const float* __restrict__ b_out,
           float* __restrict__ out,
           int T)
{
    __shared__ unsigned long long red[2][4][2][4];  // [buf][warp][token][qubit-pair]

    const int tid  = threadIdx.x;
    const int lane = tid & 31;
    const int warp = tid >> 5;
    const int cA = tid * 4;         // columns cA..cA+3
    const int cB = 512 + tid * 4;   // columns cB..cB+3

    // ---- W_in in registers, packed over qubit pairs: wi[jj][p] = (W_in[2p][j], W_in[2p+1][j])
    unsigned long long wi[8][4];
#pragma unroll
    for (int jj = 0; jj < 8; ++jj) {
        int j = (jj < 4) ? (cA + jj) : (cB + (jj - 4));
#pragma unroll
        for (int p = 0; p < 4; ++p)
            wi[jj][p] = pack2(W_in[(2 * p) * 1024 + j], W_in[(2 * p + 1) * 1024 + j]);
    }
    // ---- W_out packed over output-column pairs: wo[q][p] = (W_out[c][q], W_out[c+1][q])
    unsigned long long wo[8][4];
#pragma unroll
    for (int q = 0; q < 8; ++q) {
        wo[q][0] = pack2(W_out[(cA + 0) * 8 + q], W_out[(cA + 1) * 8 + q]);
        wo[q][1] = pack2(W_out[(cA + 2) * 8 + q], W_out[(cA + 3) * 8 + q]);
        wo[q][2] = pack2(W_out[(cB + 0) * 8 + q], W_out[(cB + 1) * 8 + q]);
        wo[q][3] = pack2(W_out[(cB + 2) * 8 + q], W_out[(cB + 3) * 8 + q]);
    }
    unsigned long long bo[4];
    bo[0] = pack2(b_out[cA + 0], b_out[cA + 1]);
    bo[1] = pack2(b_out[cA + 2], b_out[cA + 3]);
    bo[2] = pack2(b_out[cB + 0], b_out[cB + 1]);
    bo[3] = pack2(b_out[cB + 2], b_out[cB + 3]);

    const float binq = b_in[lane & 7];
    const float cthq = __cosf(theta[lane & 7]);

    const int stride2 = gridDim.x * 2;
    int t = blockIdx.x * 2;

    // prefetch first token pair (streaming loads)
    float4 p0A, p0B, p1A, p1B;
    if (t < T) {
        const float* xr = x + (size_t)t * 1024;
        p0A = ldg_cs((const float4*)(xr + cA));
        p0B = ldg_cs((const float4*)(xr + cB));
        p1A = ldg_cs((const float4*)(xr + 1024 + cA));
        p1B = ldg_cs((const float4*)(xr + 1024 + cB));
    }

    int buf = 0;
    for (; t < T; t += stride2, buf ^= 1) {
        // consume prefetched x into locals
        float xv0[8] = {p0A.x, p0A.y, p0A.z, p0A.w, p0B.x, p0B.y, p0B.z, p0B.w};
        float xv1[8] = {p1A.x, p1A.y, p1A.z, p1A.w, p1B.x, p1B.y, p1B.z, p1B.w};

        // prefetch next pair ASAP (overlaps with all compute below)
        int tn = t + stride2;
        if (tn < T) {
            const float* xr = x + (size_t)tn * 1024;
            p0A = ldg_cs((const float4*)(xr + cA));
            p0B = ldg_cs((const float4*)(xr + cB));
            p1A = ldg_cs((const float4*)(xr + 1024 + cA));
            p1B = ldg_cs((const float4*)(xr + 1024 + cB));
        }

        // ---- GEMM1: per-thread partial dot products, packed over qubit pairs
        unsigned long long acc[2][4];
#pragma unroll
        for (int p = 0; p < 4; ++p) { acc[0][p] = 0ull; acc[1][p] = 0ull; }
#pragma unroll
        for (int jj = 0; jj < 8; ++jj) {
            unsigned long long x0 = dup2(xv0[jj]);
            unsigned long long x1 = dup2(xv1[jj]);
#pragma unroll
            for (int p = 0; p < 4; ++p) {
                fma2(acc[0][p], wi[jj][p], x0);
                fma2(acc[1][p], wi[jj][p], x1);
            }
        }

        // ---- warp tree-reduce (packed adds)
#pragma unroll
        for (int off = 16; off >= 1; off >>= 1) {
#pragma unroll
            for (int tk = 0; tk < 2; ++tk)
#pragma unroll
                for (int p = 0; p < 4; ++p) {
                    unsigned long long o = __shfl_down_sync(FULL_MASK, acc[tk][p], off);
                    acc[tk][p] = add2(acc[tk][p], o);
                }
        }
        if (lane == 0) {
            ulonglong2* s = (ulonglong2*)&red[buf][warp][0][0];
            s[0] = make_ulonglong2(acc[0][0], acc[0][1]);
            s[1] = make_ulonglong2(acc[0][2], acc[0][3]);
            s[2] = make_ulonglong2(acc[1][0], acc[1][1]);
            s[3] = make_ulonglong2(acc[1][2], acc[1][3]);
        }
        __syncthreads();

        // ---- cross-warp combine + quantum layer (lanes 0-7: token0, 8-15: token1)
        const float* rf = (const float*)&red[buf][0][0][0];  // [warp][16 floats: tok*8+q]
        int off8 = lane & 15;
        float xang = binq + rf[off8] + rf[16 + off8] + rf[32 + off8] + rf[48 + off8];
        float z = cthq * __cosf(xang);
        // inclusive multiply-scan over the 8 qubits within each 8-lane group
#pragma unroll
        for (int d = 1; d < 8; d <<= 1) {
            float up = __shfl_up_sync(FULL_MASK, z, d);
            if ((lane & 7) >= d) z *= up;
        }

        // ---- GEMM2 + ReLU + streaming store, per token
#pragma unroll
        for (int tk = 0; tk < 2; ++tk) {
            unsigned long long oa[4] = {bo[0], bo[1], bo[2], bo[3]};
#pragma unroll
            for (int q = 0; q < 8; ++q) {
                float zq = __shfl_sync(FULL_MASK, z, tk * 8 + q);
                unsigned long long zz = dup2(zq);
#pragma unroll
                for (int p = 0; p < 4; ++p) fma2(oa[p], wo[q][p], zz);
            }
            float o0, o1, o2, o3, o4, o5, o6, o7;
            unpack2(oa[0], o0, o1);
            unpack2(oa[1], o2, o3);
            unpack2(oa[2], o4, o5);
            unpack2(oa[3], o6, o7);
            float4 vA = make_float4(fmaxf(o0, 0.f), fmaxf(o1, 0.f), fmaxf(o2, 0.f), fmaxf(o3, 0.f));
            float4 vB = make_float4(fmaxf(o4, 0.f), fmaxf(o5, 0.f), fmaxf(o6, 0.f), fmaxf(o7, 0.f));
            float* orow = out + (size_t)(t + tk) * 1024;
            stg_cs((float4*)(orow + cA), vA);
            stg_cs((float4*)(orow + cB), vB);
        }
    }
}

extern "C" void kernel_launch(void* const* d_in, const int* in_sizes, int n_in,
                              void* d_out, int out_size) {
    const float* x     = (const float*)d_in[0];
    const float* W_in  = (const float*)d_in[1];
    const float* b_in  = (const float*)d_in[2];
    const float* theta = (const float*)d_in[3];
    const float* W_out = (const float*)d_in[4];
    const float* b_out = (const float*)d_in[5];
    float* out = (float*)d_out;

    int T = in_sizes[0] / 1024;  // tokens = B*S = 32768
    int grid = 304;              // 2 blocks per SM on 152-SM GB300
    if (grid > (T + 1) / 2) grid = (T + 1) / 2;
    if (grid < 1) grid = 1;
    qff_kernel<<<grid, 128>>>(x, W_in, b_in, theta, W_out, b_out, out, T);
}

// round 11
// speedup vs baseline: 1.1287x; 1.1287x over previous
#include <cuda_runtime.h>
#include <cstdint>

#define FULL_MASK 0xffffffffu

__device__ __forceinline__ unsigned long long pack2(float lo, float hi) {
    unsigned long long r;
    asm("mov.b64 %0, {%1, %2};" : "=l"(r) : "f"(lo), "f"(hi));
    return r;
}
__device__ __forceinline__ unsigned long long dup2(float v) {
    unsigned long long r;
    asm("mov.b64 %0, {%1, %1};" : "=l"(r) : "f"(v));
    return r;
}
__device__ __forceinline__ void unpack2(unsigned long long v, float& lo, float& hi) {
    asm("mov.b64 {%0, %1}, %2;" : "=f"(lo), "=f"(hi) : "l"(v));
}
// d = a * b + d   (packed 2x fp32, Blackwell f32x2 pipe — 2 FMAs/instr)
__device__ __forceinline__ void fma2(unsigned long long& d, unsigned long long a, unsigned long long b) {
    asm("fma.rn.f32x2 %0, %1, %2, %0;" : "+l"(d) : "l"(a), "l"(b));
}
__device__ __forceinline__ unsigned long long add2(unsigned long long a, unsigned long long b) {
    unsigned long long r;
    asm("add.rn.f32x2 %0, %1, %2;" : "=l"(r) : "l"(a), "l"(b));
    return r;
}
// streaming (evict-first) 128-bit global load/store — x and out are single-touch
__device__ __forceinline__ float4 ldg_cs(const float4* p) {
    float4 v;
    asm volatile("ld.global.cs.v4.f32 {%0,%1,%2,%3}, [%4];"
                 : "=f"(v.x), "=f"(v.y), "=f"(v.z), "=f"(v.w) : "l"(p));
    return v;
}
__device__ __forceinline__ void stg_cs(float4* p, float4 v) {
    asm volatile("st.global.cs.v4.f32 [%0], {%1,%2,%3,%4};"
                 :: "l"(p), "f"(v.x), "f"(v.y), "f"(v.z), "f"(v.w));
}

// Analytic collapse of the quantum circuit:
//   xang = x @ W_in^T + b_in
//   z_w  = prod_{j<=w} cos(theta_j) * cos(xang_j)     (Heisenberg: Z_w -> Z_0..Z_w)
//   out  = relu(z @ W_out^T + b_out)
//
// 128 threads, 2 CTAs/SM. Each thread owns 8 E-columns for both GEMMs; weights
// in registers. 4 tokens/iteration (32 KB/SM loads in flight), distance-1
// prefetch, double-buffered reduce scratch. All 32 lanes active in quantum phase.
__global__ void __launch_bounds__(128, 2)
qff_kernel(const float* __restrict__ x,
           const float* __restrict__ W_in,
           const float* __restrict__ b_in,
           const float* __restrict__ theta,
           const float* __restrict__ W_out,
           const float* __restrict__ b_out,
           float* __restrict__ out,
           int T)
{
    __shared__ unsigned long long red[2][4][16];  // [buf][warp][tok*4 + qubit-pair]

    const int tid  = threadIdx.x;
    const int lane = tid & 31;
    const int warp = tid >> 5;
    const int cA = tid * 4;         // columns cA..cA+3
    const int cB = 512 + tid * 4;   // columns cB..cB+3

    // ---- W_in in registers, packed over qubit pairs: wi[jj][p] = (W_in[2p][j], W_in[2p+1][j])
    unsigned long long wi[8][4];
#pragma unroll
    for (int jj = 0; jj < 8; ++jj) {
        int j = (jj < 4) ? (cA + jj) : (cB + (jj - 4));
#pragma unroll
        for (int p = 0; p < 4; ++p)
            wi[jj][p] = pack2(W_in[(2 * p) * 1024 + j], W_in[(2 * p + 1) * 1024 + j]);
    }
    // ---- W_out packed over output-column pairs: wo[q][p] = (W_out[c][q], W_out[c+1][q])
    unsigned long long wo[8][4];
#pragma unroll
    for (int q = 0; q < 8; ++q) {
        wo[q][0] = pack2(W_out[(cA + 0) * 8 + q], W_out[(cA + 1) * 8 + q]);
        wo[q][1] = pack2(W_out[(cA + 2) * 8 + q], W_out[(cA + 3) * 8 + q]);
        wo[q][2] = pack2(W_out[(cB + 0) * 8 + q], W_out[(cB + 1) * 8 + q]);
        wo[q][3] = pack2(W_out[(cB + 2) * 8 + q], W_out[(cB + 3) * 8 + q]);
    }
    unsigned long long bo[4];
    bo[0] = pack2(b_out[cA + 0], b_out[cA + 1]);
    bo[1] = pack2(b_out[cA + 2], b_out[cA + 3]);
    bo[2] = pack2(b_out[cB + 0], b_out[cB + 1]);
    bo[3] = pack2(b_out[cB + 2], b_out[cB + 3]);

    const float binq = b_in[lane & 7];
    const float cthq = __cosf(theta[lane & 7]);

    const int stride4 = gridDim.x * 4;
    int t = blockIdx.x * 4;

    // prefetch first 4-token group (streaming loads)
    float4 pA[4], pB[4];
    if (t < T) {
        const float* xr = x + (size_t)t * 1024;
#pragma unroll
        for (int tk = 0; tk < 4; ++tk) {
            pA[tk] = ldg_cs((const float4*)(xr + tk * 1024 + cA));
            pB[tk] = ldg_cs((const float4*)(xr + tk * 1024 + cB));
        }
    }

    int buf = 0;
    for (; t < T; t += stride4, buf ^= 1) {
        // consume prefetched x into locals (SSA rename — no physical copy)
        float xv[4][8];
#pragma unroll
        for (int tk = 0; tk < 4; ++tk) {
            xv[tk][0] = pA[tk].x; xv[tk][1] = pA[tk].y; xv[tk][2] = pA[tk].z; xv[tk][3] = pA[tk].w;
            xv[tk][4] = pB[tk].x; xv[tk][5] = pB[tk].y; xv[tk][6] = pB[tk].z; xv[tk][7] = pB[tk].w;
        }

        // prefetch next group ASAP (overlaps with all compute below)
        int tn = t + stride4;
        if (tn < T) {
            const float* xr = x + (size_t)tn * 1024;
#pragma unroll
            for (int tk = 0; tk < 4; ++tk) {
                pA[tk] = ldg_cs((const float4*)(xr + tk * 1024 + cA));
                pB[tk] = ldg_cs((const float4*)(xr + tk * 1024 + cB));
            }
        }

        // ---- GEMM1: per-thread partial dot products, packed over qubit pairs
        unsigned long long acc[4][4];
#pragma unroll
        for (int tk = 0; tk < 4; ++tk)
#pragma unroll
            for (int p = 0; p < 4; ++p) acc[tk][p] = 0ull;
#pragma unroll
        for (int jj = 0; jj < 8; ++jj) {
#pragma unroll
            for (int tk = 0; tk < 4; ++tk) {
                unsigned long long xd = dup2(xv[tk][jj]);
#pragma unroll
                for (int p = 0; p < 4; ++p) fma2(acc[tk][p], wi[jj][p], xd);
            }
        }

        // ---- warp tree-reduce (packed adds)
#pragma unroll
        for (int off = 16; off >= 1; off >>= 1) {
#pragma unroll
            for (int tk = 0; tk < 4; ++tk)
#pragma unroll
                for (int p = 0; p < 4; ++p) {
                    unsigned long long o = __shfl_down_sync(FULL_MASK, acc[tk][p], off);
                    acc[tk][p] = add2(acc[tk][p], o);
                }
        }
        if (lane == 0) {
            ulonglong2* s = (ulonglong2*)&red[buf][warp][0];
#pragma unroll
            for (int tk = 0; tk < 4; ++tk) {
                s[tk * 2 + 0] = make_ulonglong2(acc[tk][0], acc[tk][1]);
                s[tk * 2 + 1] = make_ulonglong2(acc[tk][2], acc[tk][3]);
            }
        }
        __syncthreads();

        // ---- cross-warp combine + quantum layer
        // lane L handles token L>>3, qubit L&7 (all 32 lanes active)
        const float* rf = (const float*)&red[buf][0][0];  // [warp][32 floats: tok*8+q]
        float xang = binq + rf[lane] + rf[32 + lane] + rf[64 + lane] + rf[96 + lane];
        float z = cthq * __cosf(xang);
        // inclusive multiply-scan over the 8 qubits within each 8-lane group
#pragma unroll
        for (int d = 1; d < 8; d <<= 1) {
            float up = __shfl_up_sync(FULL_MASK, z, d);
            if ((lane & 7) >= d) z *= up;
        }

        // ---- GEMM2 + ReLU + streaming store, per token
#pragma unroll
        for (int tk = 0; tk < 4; ++tk) {
            unsigned long long oa[4] = {bo[0], bo[1], bo[2], bo[3]};
#pragma unroll
            for (int q = 0; q < 8; ++q) {
                float zq = __shfl_sync(FULL_MASK, z, tk * 8 + q);
                unsigned long long zz = dup2(zq);
#pragma unroll
                for (int p = 0; p < 4; ++p) fma2(oa[p], wo[q][p], zz);
            }
            float o0, o1, o2, o3, o4, o5, o6, o7;
            unpack2(oa[0], o0, o1);
            unpack2(oa[1], o2, o3);
            unpack2(oa[2], o4, o5);
            unpack2(oa[3], o6, o7);
            float4 vA = make_float4(fmaxf(o0, 0.f), fmaxf(o1, 0.f), fmaxf(o2, 0.f), fmaxf(o3, 0.f));
            float4 vB = make_float4(fmaxf(o4, 0.f), fmaxf(o5, 0.f), fmaxf(o6, 0.f), fmaxf(o7, 0.f));
            float* orow = out + (size_t)(t + tk) * 1024;
            stg_cs((float4*)(orow + cA), vA);
            stg_cs((float4*)(orow + cB), vB);
        }
    }
}

extern "C" void kernel_launch(void* const* d_in, const int* in_sizes, int n_in,
                              void* d_out, int out_size) {
    const float* x     = (const float*)d_in[0];
    const float* W_in  = (const float*)d_in[1];
    const float* b_in  = (const float*)d_in[2];
    const float* theta = (const float*)d_in[3];
    const float* W_out = (const float*)d_in[4];
    const float* b_out = (const float*)d_in[5];
    float* out = (float*)d_out;

    int T = in_sizes[0] / 1024;  // tokens = B*S = 32768 (divisible by 4)
    int grid = 304;              // 2 blocks per SM on 152-SM GB300
    if (grid > (T + 3) / 4) grid = (T + 3) / 4;
    if (grid < 1) grid = 1;
    qff_kernel<<<grid, 128>>>(x, W_in, b_in, theta, W_out, b_out, out, T);
}